// round 5
// baseline (speedup 1.0000x reference)
#include <cuda_runtime.h>
#include <math.h>

#define BB 4
#define LL 2048
#define DM 512
#define NH 2
#define DK 64
#define HD 128            // NH*DK
#define OUT0 (BB*LL*DM)   // 4194304 floats; attn follows
#define NROWS (BB*NH*LL)  // 16384 attention rows

typedef unsigned long long ull;

// scratch (static device globals — no allocations)
__device__ float g_q[BB*LL*HD];
__device__ float g_k[BB*LL*HD];
__device__ float g_v[BB*LL*HD];
__device__ float g_oh[BB*LL*HD];
__device__ float g_rowsum[NROWS];   // sum exp(s) per row, then lse in place

__device__ __forceinline__ float fast_tanh(float x) {
    float y;
    asm("tanh.approx.f32 %0, %1;" : "=f"(y) : "f"(x));
    return y;
}
// packed fp32x2 FMA (sm_103a FFMA2): d = a*b + d, 2 MACs/instr
__device__ __forceinline__ void ffma2(ull& d, ull a, ull b) {
    asm("fma.rn.f32x2 %0, %1, %2, %0;" : "+l"(d) : "l"(a), "l"(b));
}
__device__ __forceinline__ ull dup2(float x) {
    ull r; asm("mov.b64 %0, {%1, %1};" : "=l"(r) : "f"(x)); return r;
}
__device__ __forceinline__ ull pack2(float x, float y) {
    ull r; asm("mov.b64 %0, {%1, %2};" : "=l"(r) : "f"(x), "f"(y)); return r;
}
__device__ __forceinline__ float2 unpack2(ull v) {
    float2 r; asm("mov.b64 {%0, %1}, %2;" : "=f"(r.x), "=f"(r.y) : "l"(v)); return r;
}

// ---------------------------------------------------------------------------
__global__ __launch_bounds__(256) void zero_rowsum_kernel(float* __restrict__ rs)
{
    rs[blockIdx.x * 256 + threadIdx.x] = 0.0f;
}

__global__ __launch_bounds__(256) void lse_kernel(float* __restrict__ rs)
{
    int i = blockIdx.x * 256 + threadIdx.x;
    rs[i] = logf(rs[i]);
}

// ---------------------------------------------------------------------------
// Tiled GEMM: C[M,N] = A[M,K] @ W[K,N] + bias[N]
// 128x64 C tile, BK=16, 256 threads, 8x4 per thread, f32x2 accumulators.
// ---------------------------------------------------------------------------
__device__ __forceinline__ void gemm_core_128x64(
    const float* __restrict__ A, const float* __restrict__ W,
    const float* __restrict__ bias, float* __restrict__ C,
    int N, int K, int bm, int bn, int ldA, int ldC)
{
    __shared__ float As[16][132];  // [k][m], m=0..127
    __shared__ float Ws[16][68];   // [k][n]
    const int tid = threadIdx.x;
    const int ty = tid >> 4, tx = tid & 15;
    ull accp[8][2] = {};

    for (int k0 = 0; k0 < K; k0 += 16) {
#pragma unroll
        for (int r = 0; r < 2; r++) {           // 512 f4: 128 rows x 4 f4
            int idx = tid + r * 256;
            int m = idx >> 2, k4 = idx & 3;
            float4 t = *reinterpret_cast<const float4*>(
                &A[(size_t)(bm + m) * ldA + k0 + k4 * 4]);
            As[k4 * 4 + 0][m] = t.x;
            As[k4 * 4 + 1][m] = t.y;
            As[k4 * 4 + 2][m] = t.z;
            As[k4 * 4 + 3][m] = t.w;
        }
        {                                        // 256 f4: 16 rows x 16 f4
            int kk = tid >> 4, n4 = tid & 15;
            *reinterpret_cast<float4*>(&Ws[kk][n4 * 4]) =
                *reinterpret_cast<const float4*>(
                    &W[(size_t)(k0 + kk) * N + bn + n4 * 4]);
        }
        __syncthreads();
#pragma unroll
        for (int kk = 0; kk < 16; kk++) {
            float4 a0 = *reinterpret_cast<const float4*>(&As[kk][ty * 4]);
            float4 a1 = *reinterpret_cast<const float4*>(&As[kk][64 + ty * 4]);
            float4 b  = *reinterpret_cast<const float4*>(&Ws[kk][tx * 4]);
            ull bp0 = pack2(b.x, b.y), bp1 = pack2(b.z, b.w);
            float av[8] = {a0.x, a0.y, a0.z, a0.w, a1.x, a1.y, a1.z, a1.w};
#pragma unroll
            for (int i = 0; i < 8; i++) {
                ull ai = dup2(av[i]);
                ffma2(accp[i][0], ai, bp0);
                ffma2(accp[i][1], ai, bp1);
            }
        }
        __syncthreads();
    }
    float4 bs = *reinterpret_cast<const float4*>(&bias[bn + tx * 4]);
#pragma unroll
    for (int i = 0; i < 8; i++) {
        int m = bm + ((i < 4) ? (ty * 4 + i) : (64 + ty * 4 + i - 4));
        float2 p0 = unpack2(accp[i][0]);
        float2 p1 = unpack2(accp[i][1]);
        float4 o = make_float4(p0.x + bs.x, p0.y + bs.y,
                               p1.x + bs.z, p1.y + bs.w);
        *reinterpret_cast<float4*>(&C[(size_t)m * ldC + bn + tx * 4]) = o;
    }
}

__global__ __launch_bounds__(256) void gemm_bias_kernel(
    const float* __restrict__ A, const float* __restrict__ W,
    const float* __restrict__ bias, float* __restrict__ C,
    int M, int N, int K)
{
    gemm_core_128x64(A, W, bias, C, N, K,
                     blockIdx.y * 128, blockIdx.x * 64, K, N);
}

// Fused QKV: z selects which projection.
__global__ __launch_bounds__(256) void qkv_kernel(
    const float* __restrict__ Q, const float* __restrict__ K,
    const float* __restrict__ V,
    const float* __restrict__ Wq, const float* __restrict__ Wk,
    const float* __restrict__ Wv,
    const float* __restrict__ bq, const float* __restrict__ bk,
    const float* __restrict__ bv,
    float* __restrict__ q, float* __restrict__ k, float* __restrict__ v)
{
    const float *A, *W, *bias;
    float* C;
    if (blockIdx.z == 0)      { A = Q; W = Wq; bias = bq; C = q; }
    else if (blockIdx.z == 1) { A = K; W = Wk; bias = bk; C = k; }
    else                      { A = V; W = Wv; bias = bv; C = v; }
    gemm_core_128x64(A, W, bias, C, HD, DM,
                     blockIdx.y * 128, blockIdx.x * 64, DM, HD);
}

// ---------------------------------------------------------------------------
// Scores: S[i,j] = tanh(dot(q_i,k_j)/8)*10, masked -> -10. Writes raw clipped
// scores to attn AND accumulates per-row sum(exp(s)) into g_rowsum (atomics).
// 128x128 tile, 8x8 per thread, full DK=64 in dynamic smem, 1 sync, f32x2.
// ---------------------------------------------------------------------------
__global__ __launch_bounds__(256) void scores_kernel(
    const float* __restrict__ q, const float* __restrict__ k,
    const int* __restrict__ mask, float* __restrict__ attn,
    float* __restrict__ rowsum)
{
    extern __shared__ float sm[];
    float* Qs = sm;                 // [64][132]  (d-major, i inner)
    float* Ks = sm + 64 * 132;      // [64][132]
    const int bh = blockIdx.z;
    const int b = bh >> 1, h = bh & 1;
    const int i0 = blockIdx.y * 128, j0 = blockIdx.x * 128;
    const int tid = threadIdx.x;
    const int ty = tid >> 4, tx = tid & 15;

#pragma unroll
    for (int r = 0; r < 8; r++) {           // 2048 f4 per tensor
        int idx = tid + r * 256;
        int k4q = idx & 3, i = (idx >> 2) & 127, cq = idx >> 9;
        int dbase = cq * 16 + k4q * 4;
        float4 tq = *reinterpret_cast<const float4*>(
            &q[(size_t)(b * LL + i0 + i) * HD + h * DK + dbase]);
        Qs[(dbase + 0) * 132 + i] = tq.x;
        Qs[(dbase + 1) * 132 + i] = tq.y;
        Qs[(dbase + 2) * 132 + i] = tq.z;
        Qs[(dbase + 3) * 132 + i] = tq.w;
        float4 tk = *reinterpret_cast<const float4*>(
            &k[(size_t)(b * LL + j0 + i) * HD + h * DK + dbase]);
        Ks[(dbase + 0) * 132 + i] = tk.x;
        Ks[(dbase + 1) * 132 + i] = tk.y;
        Ks[(dbase + 2) * 132 + i] = tk.z;
        Ks[(dbase + 3) * 132 + i] = tk.w;
    }
    __syncthreads();

    ull accp[8][4] = {};   // pairs along j: accp[i][jp] = (j=2jp, j=2jp+1)
#pragma unroll
    for (int kk = 0; kk < 64; kk++) {
        float4 a0 = *reinterpret_cast<const float4*>(&Qs[kk * 132 + ty * 4]);
        float4 a1 = *reinterpret_cast<const float4*>(&Qs[kk * 132 + 64 + ty * 4]);
        float4 b0 = *reinterpret_cast<const float4*>(&Ks[kk * 132 + tx * 4]);
        float4 b1 = *reinterpret_cast<const float4*>(&Ks[kk * 132 + 64 + tx * 4]);
        ull bp[4] = {pack2(b0.x, b0.y), pack2(b0.z, b0.w),
                     pack2(b1.x, b1.y), pack2(b1.z, b1.w)};
        float av[8] = {a0.x, a0.y, a0.z, a0.w, a1.x, a1.y, a1.z, a1.w};
#pragma unroll
        for (int i = 0; i < 8; i++) {
            ull ai = dup2(av[i]);
#pragma unroll
            for (int jp = 0; jp < 4; jp++) ffma2(accp[i][jp], ai, bp[jp]);
        }
    }

    const int jj0 = j0 + tx * 4;
    const int jj1 = j0 + 64 + tx * 4;
    int4 m0 = *reinterpret_cast<const int4*>(&mask[b * LL + jj0]);
    int4 m1 = *reinterpret_cast<const int4*>(&mask[b * LL + jj1]);
    const int msk[8] = {m0.x, m0.y, m0.z, m0.w, m1.x, m1.y, m1.z, m1.w};
#pragma unroll
    for (int i = 0; i < 8; i++) {
        int ii = i0 + ((i < 4) ? (ty * 4 + i) : (64 + ty * 4 + i - 4));
        float s[8];
        float2 p;
        p = unpack2(accp[i][0]); s[0] = p.x; s[1] = p.y;
        p = unpack2(accp[i][1]); s[2] = p.x; s[3] = p.y;
        p = unpack2(accp[i][2]); s[4] = p.x; s[5] = p.y;
        p = unpack2(accp[i][3]); s[6] = p.x; s[7] = p.y;
        float w[8];
#pragma unroll
        for (int j = 0; j < 8; j++)
            w[j] = msk[j] ? -10.0f : fast_tanh(s[j] * 0.125f) * 10.0f;
        float* row = &attn[((size_t)bh * LL + ii) * LL];
        *reinterpret_cast<float4*>(&row[jj0]) = make_float4(w[0], w[1], w[2], w[3]);
        *reinterpret_cast<float4*>(&row[jj1]) = make_float4(w[4], w[5], w[6], w[7]);
        float rs = __expf(w[0]) + __expf(w[1]) + __expf(w[2]) + __expf(w[3])
                 + __expf(w[4]) + __expf(w[5]) + __expf(w[6]) + __expf(w[7]);
#pragma unroll
        for (int o = 8; o; o >>= 1) rs += __shfl_xor_sync(0xffffffffu, rs, o);
        if (tx == 0) atomicAdd(&rowsum[bh * LL + ii], rs);
    }
}

// ---------------------------------------------------------------------------
// av: reads raw scores, w = s - lse[row]; writes w back to attn (final
// log-softmax output) and computes oh[i,d] = sum_j w * v[j,d].
// 128(i) x 64(d) tile, 8x4 per thread, BK=32, f32x2. 128 blocks (one wave).
// ---------------------------------------------------------------------------
__global__ __launch_bounds__(256) void av_kernel(
    float* __restrict__ attn, const float* __restrict__ v,
    const float* __restrict__ lse, float* __restrict__ oh)
{
    __shared__ float As[32][132];  // [j][i]
    __shared__ float Vs[32][68];   // [j][d]
    __shared__ float lse_s[128];
    const int bh = blockIdx.y;
    const int b = bh >> 1, h = bh & 1;
    const int i0 = blockIdx.x * 128;
    const int tid = threadIdx.x;
    const int ty = tid >> 4, tx = tid & 15;

    if (tid < 128) lse_s[tid] = lse[bh * LL + i0 + tid];
    __syncthreads();

    ull accp[8][2] = {};
    for (int k0 = 0; k0 < LL; k0 += 32) {
#pragma unroll
        for (int r = 0; r < 4; r++) {
            int idx = tid + r * 256;      // 1024 f4: 128 rows x 8 f4
            int i = idx >> 3, j4 = idx & 7;
            float* gp = &attn[((size_t)bh * LL + i0 + i) * LL + k0 + j4 * 4];
            float4 t = *reinterpret_cast<const float4*>(gp);
            float l = lse_s[i];
            t.x -= l; t.y -= l; t.z -= l; t.w -= l;
            *reinterpret_cast<float4*>(gp) = t;          // final attn out
            As[j4 * 4 + 0][i] = t.x;
            As[j4 * 4 + 1][i] = t.y;
            As[j4 * 4 + 2][i] = t.z;
            As[j4 * 4 + 3][i] = t.w;
        }
#pragma unroll
        for (int r = 0; r < 2; r++) {
            int idx = tid + r * 256;      // 512 f4: 32 rows x 16 f4
            int jj = idx >> 4, d4 = idx & 15;
            *reinterpret_cast<float4*>(&Vs[jj][d4 * 4]) =
                *reinterpret_cast<const float4*>(
                    &v[(size_t)(b * LL + k0 + jj) * HD + h * DK + d4 * 4]);
        }
        __syncthreads();
#pragma unroll
        for (int kk = 0; kk < 32; kk++) {
            float4 a0 = *reinterpret_cast<const float4*>(&As[kk][ty * 4]);
            float4 a1 = *reinterpret_cast<const float4*>(&As[kk][64 + ty * 4]);
            float4 bb = *reinterpret_cast<const float4*>(&Vs[kk][tx * 4]);
            ull bp0 = pack2(bb.x, bb.y), bp1 = pack2(bb.z, bb.w);
            float av[8] = {a0.x, a0.y, a0.z, a0.w, a1.x, a1.y, a1.z, a1.w};
#pragma unroll
            for (int i = 0; i < 8; i++) {
                ull ai = dup2(av[i]);
                ffma2(accp[i][0], ai, bp0);
                ffma2(accp[i][1], ai, bp1);
            }
        }
        __syncthreads();
    }
#pragma unroll
    for (int i = 0; i < 8; i++) {
        int ii = i0 + ((i < 4) ? (ty * 4 + i) : (64 + ty * 4 + i - 4));
        float2 p0 = unpack2(accp[i][0]);
        float2 p1 = unpack2(accp[i][1]);
        float4 o = make_float4(p0.x, p0.y, p1.x, p1.y);
        *reinterpret_cast<float4*>(
            &oh[(size_t)(b * LL + ii) * HD + h * DK + tx * 4]) = o;
    }
}

// ---------------------------------------------------------------------------
extern "C" void kernel_launch(void* const* d_in, const int* in_sizes, int n_in,
                              void* d_out, int out_size)
{
    const float* Q  = (const float*)d_in[0];
    const float* K  = (const float*)d_in[1];
    const float* V  = (const float*)d_in[2];
    const int*   mask = (const int*)d_in[3];
    const float* Wq = (const float*)d_in[4];
    const float* bq = (const float*)d_in[5];
    const float* Wk = (const float*)d_in[6];
    const float* bk = (const float*)d_in[7];
    const float* Wv = (const float*)d_in[8];
    const float* bv = (const float*)d_in[9];
    const float* Wo = (const float*)d_in[10];
    const float* bo = (const float*)d_in[11];

    float* out  = (float*)d_out;          // [B, Lq, 512]
    float* attn = out + OUT0;             // [B, H, Lq, Lk]

    float *q, *k, *v, *oh, *rs;
    cudaGetSymbolAddress((void**)&q,  g_q);
    cudaGetSymbolAddress((void**)&k,  g_k);
    cudaGetSymbolAddress((void**)&v,  g_v);
    cudaGetSymbolAddress((void**)&oh, g_oh);
    cudaGetSymbolAddress((void**)&rs, g_rowsum);

    const int M = BB * LL;                // 8192
    const int SCORES_SMEM = 2 * 64 * 132 * 4;   // 67584 B
    cudaFuncSetAttribute(scores_kernel,
                         cudaFuncAttributeMaxDynamicSharedMemorySize, SCORES_SMEM);

    // 0) zero the rowsum accumulator
    zero_rowsum_kernel<<<NROWS / 256, 256>>>(rs);

    // 1) fused projections: [8192,512] @ [512,128] x3
    dim3 gp(HD / 64, M / 128, 3);
    qkv_kernel<<<gp, 256>>>(Q, K, V, Wq, Wk, Wv, bq, bk, bv, q, k, v);

    // 2) scores + tanh clip + mask -> attn (raw) + rowsum atomics
    dim3 gs(LL / 128, LL / 128, BB * NH);
    scores_kernel<<<gs, 256, SCORES_SMEM>>>(q, k, mask, attn, rs);

    // 3) rowsum -> lse
    lse_kernel<<<NROWS / 256, 256>>>(rs);

    // 4) attn = s - lse (written back) ; oh = attn @ v
    dim3 ga(LL / 128, BB * NH);
    av_kernel<<<ga, 256>>>(attn, v, rs, oh);

    // 5) out = oh @ Wo + bo : [8192,128] @ [128,512]
    dim3 go(DM / 64, M / 128);
    gemm_bias_kernel<<<go, 256>>>(oh, Wo, bo, out, M, DM, HD);
}

// round 8
// speedup vs baseline: 1.3013x; 1.3013x over previous
#include <cuda_runtime.h>
#include <cuda_bf16.h>
#include <math.h>
#include <stdint.h>

#define BB 4
#define LL 2048
#define DM 512
#define NH 2
#define DK 64
#define HD 128            // NH*DK
#define OUT0 (BB*LL*DM)   // 4194304 floats; attn follows
#define NROWS (BB*NH*LL)  // 16384 attention rows

// scratch (static device globals — no allocations)
__device__ float g_q[BB*LL*HD];
__device__ float g_k[BB*LL*HD];
__device__ float g_v[BB*LL*HD];
__device__ float g_oh[BB*LL*HD];
__device__ float g_rowsum[NROWS];   // sum exp(s) per row, then lse in place

__device__ __forceinline__ float fast_tanh(float x) {
    float y;
    asm("tanh.approx.f32 %0, %1;" : "=f"(y) : "f"(x));
    return y;
}

// bf16 HMMA: D(16x8,f32) += A(16x16,bf16 row) * B(16x8,bf16 col)
__device__ __forceinline__ void mma16816(float* d, const uint32_t* a,
                                         const uint32_t* b) {
    asm volatile(
        "mma.sync.aligned.m16n8k16.row.col.f32.bf16.bf16.f32 "
        "{%0,%1,%2,%3}, {%4,%5,%6,%7}, {%8,%9}, {%0,%1,%2,%3};"
        : "+f"(d[0]), "+f"(d[1]), "+f"(d[2]), "+f"(d[3])
        : "r"(a[0]), "r"(a[1]), "r"(a[2]), "r"(a[3]), "r"(b[0]), "r"(b[1]));
}

// ---------------------------------------------------------------------------
__global__ __launch_bounds__(256) void zero_rowsum_kernel(float* __restrict__ rs)
{
    rs[blockIdx.x * 256 + threadIdx.x] = 0.0f;
}

__global__ __launch_bounds__(256) void lse_kernel(float* __restrict__ rs)
{
    int i = blockIdx.x * 256 + threadIdx.x;
    rs[i] = logf(rs[i]);
}

// ---------------------------------------------------------------------------
// Tiled GEMM: C[M,N] = A[M,K] @ W[K,N] + bias[N]   (scalar FFMA, R4-proven)
// 128x64 C tile, BK=16, 256 threads, 8x4 per thread.
// ---------------------------------------------------------------------------
__device__ __forceinline__ void gemm_core_128x64(
    const float* __restrict__ A, const float* __restrict__ W,
    const float* __restrict__ bias, float* __restrict__ C,
    int N, int K, int bm, int bn, int ldA, int ldC)
{
    __shared__ float As[16][132];
    __shared__ float Ws[16][68];
    const int tid = threadIdx.x;
    const int ty = tid >> 4, tx = tid & 15;
    float acc[8][4] = {};

    for (int k0 = 0; k0 < K; k0 += 16) {
#pragma unroll
        for (int r = 0; r < 2; r++) {
            int idx = tid + r * 256;
            int m = idx >> 2, k4 = idx & 3;
            float4 t = *reinterpret_cast<const float4*>(
                &A[(size_t)(bm + m) * ldA + k0 + k4 * 4]);
            As[k4 * 4 + 0][m] = t.x;
            As[k4 * 4 + 1][m] = t.y;
            As[k4 * 4 + 2][m] = t.z;
            As[k4 * 4 + 3][m] = t.w;
        }
        {
            int kk = tid >> 4, n4 = tid & 15;
            *reinterpret_cast<float4*>(&Ws[kk][n4 * 4]) =
                *reinterpret_cast<const float4*>(
                    &W[(size_t)(k0 + kk) * N + bn + n4 * 4]);
        }
        __syncthreads();
#pragma unroll
        for (int kk = 0; kk < 16; kk++) {
            float4 a0 = *reinterpret_cast<const float4*>(&As[kk][ty * 4]);
            float4 a1 = *reinterpret_cast<const float4*>(&As[kk][64 + ty * 4]);
            float4 b  = *reinterpret_cast<const float4*>(&Ws[kk][tx * 4]);
            float av[8] = {a0.x, a0.y, a0.z, a0.w, a1.x, a1.y, a1.z, a1.w};
            float bv[4] = {b.x, b.y, b.z, b.w};
#pragma unroll
            for (int i = 0; i < 8; i++)
#pragma unroll
                for (int j = 0; j < 4; j++)
                    acc[i][j] += av[i] * bv[j];
        }
        __syncthreads();
    }
    float4 bs = *reinterpret_cast<const float4*>(&bias[bn + tx * 4]);
#pragma unroll
    for (int i = 0; i < 8; i++) {
        int m = bm + ((i < 4) ? (ty * 4 + i) : (64 + ty * 4 + i - 4));
        float4 o = make_float4(acc[i][0] + bs.x, acc[i][1] + bs.y,
                               acc[i][2] + bs.z, acc[i][3] + bs.w);
        *reinterpret_cast<float4*>(&C[(size_t)m * ldC + bn + tx * 4]) = o;
    }
}

__global__ __launch_bounds__(256) void gemm_bias_kernel(
    const float* __restrict__ A, const float* __restrict__ W,
    const float* __restrict__ bias, float* __restrict__ C,
    int M, int N, int K)
{
    gemm_core_128x64(A, W, bias, C, N, K,
                     blockIdx.y * 128, blockIdx.x * 64, K, N);
}

__global__ __launch_bounds__(256) void qkv_kernel(
    const float* __restrict__ Q, const float* __restrict__ K,
    const float* __restrict__ V,
    const float* __restrict__ Wq, const float* __restrict__ Wk,
    const float* __restrict__ Wv,
    const float* __restrict__ bq, const float* __restrict__ bk,
    const float* __restrict__ bv,
    float* __restrict__ q, float* __restrict__ k, float* __restrict__ v)
{
    const float *A, *W, *bias;
    float* C;
    if (blockIdx.z == 0)      { A = Q; W = Wq; bias = bq; C = q; }
    else if (blockIdx.z == 1) { A = K; W = Wk; bias = bk; C = k; }
    else                      { A = V; W = Wv; bias = bv; C = v; }
    gemm_core_128x64(A, W, bias, C, HD, DM,
                     blockIdx.y * 128, blockIdx.x * 64, DM, HD);
}

// ---------------------------------------------------------------------------
// Tensor-core scores via mma.sync bf16 hi/lo split (3 pairings).
// 128x128 tile, 8 warps (4m x 2n), each warp 32x64 (2x8 m16n8 subtiles).
// Writes clipped scores directly to attn + per-row sum(exp) atomics.
// ---------------------------------------------------------------------------
#define SLD 72                       // smem row pitch in bf16 elements
#define O_QH 0
#define O_QL (128*SLD)
#define O_KH (2*128*SLD)
#define O_KL (3*128*SLD)
#define SCORES_DYN (4*128*SLD*2)     // 73728 bytes

__global__ __launch_bounds__(256) void scores_mma_kernel(
    const float* __restrict__ q, const float* __restrict__ k,
    const int* __restrict__ mask, float* __restrict__ attn,
    float* __restrict__ rowsum)
{
    extern __shared__ __align__(16) __nv_bfloat16 sm[];
    __shared__ int s_mask[128];

    const int tid = threadIdx.x, wid = tid >> 5, lane = tid & 31;
    const int bh = blockIdx.z, b = bh >> 1, h = bh & 1;
    const int i0 = blockIdx.y * 128, j0 = blockIdx.x * 128;
    const int wm = wid >> 1, wn = wid & 1;

    if (tid < 128) s_mask[tid] = mask[b * LL + j0 + tid];

    // fill q/k tiles as bf16 hi/lo, rows padded to SLD
#pragma unroll
    for (int r = 0; r < 8; r++) {
        int idx = tid + r * 256;          // 2048 = 128 rows x 16 f4
        int m = idx >> 4, d = (idx & 15) * 4;
        {
            float4 t = *reinterpret_cast<const float4*>(
                &q[(size_t)(b * LL + i0 + m) * HD + h * DK + d]);
            __nv_bfloat16 h0 = __float2bfloat16(t.x), h1 = __float2bfloat16(t.y);
            __nv_bfloat16 h2 = __float2bfloat16(t.z), h3 = __float2bfloat16(t.w);
            __nv_bfloat16 l0 = __float2bfloat16(t.x - __bfloat162float(h0));
            __nv_bfloat16 l1 = __float2bfloat16(t.y - __bfloat162float(h1));
            __nv_bfloat16 l2 = __float2bfloat16(t.z - __bfloat162float(h2));
            __nv_bfloat16 l3 = __float2bfloat16(t.w - __bfloat162float(h3));
            __nv_bfloat162 hp0(h0, h1), hp1(h2, h3), lp0(l0, l1), lp1(l2, l3);
            *reinterpret_cast<uint2*>(&sm[O_QH + m * SLD + d]) =
                make_uint2(*(uint32_t*)&hp0, *(uint32_t*)&hp1);
            *reinterpret_cast<uint2*>(&sm[O_QL + m * SLD + d]) =
                make_uint2(*(uint32_t*)&lp0, *(uint32_t*)&lp1);
        }
        {
            float4 t = *reinterpret_cast<const float4*>(
                &k[(size_t)(b * LL + j0 + m) * HD + h * DK + d]);
            __nv_bfloat16 h0 = __float2bfloat16(t.x), h1 = __float2bfloat16(t.y);
            __nv_bfloat16 h2 = __float2bfloat16(t.z), h3 = __float2bfloat16(t.w);
            __nv_bfloat16 l0 = __float2bfloat16(t.x - __bfloat162float(h0));
            __nv_bfloat16 l1 = __float2bfloat16(t.y - __bfloat162float(h1));
            __nv_bfloat16 l2 = __float2bfloat16(t.z - __bfloat162float(h2));
            __nv_bfloat16 l3 = __float2bfloat16(t.w - __bfloat162float(h3));
            __nv_bfloat162 hp0(h0, h1), hp1(h2, h3), lp0(l0, l1), lp1(l2, l3);
            *reinterpret_cast<uint2*>(&sm[O_KH + m * SLD + d]) =
                make_uint2(*(uint32_t*)&hp0, *(uint32_t*)&hp1);
            *reinterpret_cast<uint2*>(&sm[O_KL + m * SLD + d]) =
                make_uint2(*(uint32_t*)&lp0, *(uint32_t*)&lp1);
        }
    }
    __syncthreads();

    float acc[2][8][4];
#pragma unroll
    for (int mt = 0; mt < 2; mt++)
#pragma unroll
        for (int nt = 0; nt < 8; nt++)
#pragma unroll
            for (int r = 0; r < 4; r++) acc[mt][nt][r] = 0.0f;

    const int gq = lane >> 2;            // group row/col id
    const int qc = (lane & 3) * 2;       // k-offset within fragment

#pragma unroll
    for (int ks = 0; ks < 4; ks++) {
        const int kc = ks * 16 + qc;
        uint32_t ah[2][4], al[2][4];
#pragma unroll
        for (int mt = 0; mt < 2; mt++) {
            int gr = wm * 32 + mt * 16 + gq;
            ah[mt][0] = *reinterpret_cast<const uint32_t*>(&sm[O_QH + gr * SLD + kc]);
            ah[mt][1] = *reinterpret_cast<const uint32_t*>(&sm[O_QH + (gr + 8) * SLD + kc]);
            ah[mt][2] = *reinterpret_cast<const uint32_t*>(&sm[O_QH + gr * SLD + kc + 8]);
            ah[mt][3] = *reinterpret_cast<const uint32_t*>(&sm[O_QH + (gr + 8) * SLD + kc + 8]);
            al[mt][0] = *reinterpret_cast<const uint32_t*>(&sm[O_QL + gr * SLD + kc]);
            al[mt][1] = *reinterpret_cast<const uint32_t*>(&sm[O_QL + (gr + 8) * SLD + kc]);
            al[mt][2] = *reinterpret_cast<const uint32_t*>(&sm[O_QL + gr * SLD + kc + 8]);
            al[mt][3] = *reinterpret_cast<const uint32_t*>(&sm[O_QL + (gr + 8) * SLD + kc + 8]);
        }
#pragma unroll
        for (int nt = 0; nt < 8; nt++) {
            int jn = wn * 64 + nt * 8 + gq;
            uint32_t bh2[2], bl2[2];
            bh2[0] = *reinterpret_cast<const uint32_t*>(&sm[O_KH + jn * SLD + kc]);
            bh2[1] = *reinterpret_cast<const uint32_t*>(&sm[O_KH + jn * SLD + kc + 8]);
            bl2[0] = *reinterpret_cast<const uint32_t*>(&sm[O_KL + jn * SLD + kc]);
            bl2[1] = *reinterpret_cast<const uint32_t*>(&sm[O_KL + jn * SLD + kc + 8]);
#pragma unroll
            for (int mt = 0; mt < 2; mt++) {
                mma16816(acc[mt][nt], ah[mt], bh2);
                mma16816(acc[mt][nt], al[mt], bh2);
                mma16816(acc[mt][nt], ah[mt], bl2);
            }
        }
    }

    // epilogue: tanh+mask, direct gmem store, rowsum atomics
#pragma unroll
    for (int mt = 0; mt < 2; mt++) {
        int r0 = wm * 32 + mt * 16 + gq;     // local row of d0,d1
        int r1 = r0 + 8;                     // local row of d2,d3
        float rs0 = 0.0f, rs1 = 0.0f;
#pragma unroll
        for (int nt = 0; nt < 8; nt++) {
            int c = wn * 64 + nt * 8 + (lane & 3) * 2;   // local col
            int mk0 = s_mask[c], mk1 = s_mask[c + 1];
            float w0 = mk0 ? -10.0f : fast_tanh(acc[mt][nt][0] * 0.125f) * 10.0f;
            float w1 = mk1 ? -10.0f : fast_tanh(acc[mt][nt][1] * 0.125f) * 10.0f;
            float w2 = mk0 ? -10.0f : fast_tanh(acc[mt][nt][2] * 0.125f) * 10.0f;
            float w3 = mk1 ? -10.0f : fast_tanh(acc[mt][nt][3] * 0.125f) * 10.0f;
            *reinterpret_cast<float2*>(
                &attn[((size_t)bh * LL + i0 + r0) * LL + j0 + c]) =
                make_float2(w0, w1);
            *reinterpret_cast<float2*>(
                &attn[((size_t)bh * LL + i0 + r1) * LL + j0 + c]) =
                make_float2(w2, w3);
            rs0 += __expf(w0) + __expf(w1);
            rs1 += __expf(w2) + __expf(w3);
        }
        rs0 += __shfl_xor_sync(0xffffffffu, rs0, 1);
        rs0 += __shfl_xor_sync(0xffffffffu, rs0, 2);
        rs1 += __shfl_xor_sync(0xffffffffu, rs1, 1);
        rs1 += __shfl_xor_sync(0xffffffffu, rs1, 2);
        if ((lane & 3) == 0) {
            atomicAdd(&rowsum[bh * LL + i0 + r0], rs0);
            atomicAdd(&rowsum[bh * LL + i0 + r1], rs1);
        }
    }
}

// ---------------------------------------------------------------------------
// av: reads raw scores, w = s - lse[row]; writes w back to attn and computes
// oh[i,d] = sum_j w * v[j,d]. 64x64 tile, 4x4/thread, BK=32 (R4-proven).
// ---------------------------------------------------------------------------
__global__ __launch_bounds__(256) void av_kernel(
    float* __restrict__ attn, const float* __restrict__ v,
    const float* __restrict__ lse, float* __restrict__ oh)
{
    __shared__ float As[32][68];
    __shared__ float Vs[32][68];
    __shared__ float lse_s[64];
    const int bh = blockIdx.y;
    const int b = bh >> 1, h = bh & 1;
    const int i0 = blockIdx.x * 64;
    const int tid = threadIdx.x;
    const int ty = tid >> 4, tx = tid & 15;

    if (tid < 64) lse_s[tid] = lse[bh * LL + i0 + tid];
    __syncthreads();

    float acc[4][4] = {};
    for (int k0 = 0; k0 < LL; k0 += 32) {
#pragma unroll
        for (int r = 0; r < 2; r++) {
            int idx = tid + r * 256;
            int i = idx >> 3, j4 = idx & 7;
            float* gp = &attn[((size_t)bh * LL + i0 + i) * LL + k0 + j4 * 4];
            float4 t = *reinterpret_cast<const float4*>(gp);
            float l = lse_s[i];
            t.x -= l; t.y -= l; t.z -= l; t.w -= l;
            *reinterpret_cast<float4*>(gp) = t;
            As[j4 * 4 + 0][i] = t.x;
            As[j4 * 4 + 1][i] = t.y;
            As[j4 * 4 + 2][i] = t.z;
            As[j4 * 4 + 3][i] = t.w;
        }
#pragma unroll
        for (int r = 0; r < 2; r++) {
            int idx = tid + r * 256;
            int jj = idx >> 4, d4 = idx & 15;
            *reinterpret_cast<float4*>(&Vs[jj][d4 * 4]) =
                *reinterpret_cast<const float4*>(
                    &v[(size_t)(b * LL + k0 + jj) * HD + h * DK + d4 * 4]);
        }
        __syncthreads();
#pragma unroll
        for (int kk = 0; kk < 32; kk++) {
            float4 a = *reinterpret_cast<const float4*>(&As[kk][ty * 4]);
            float4 bb = *reinterpret_cast<const float4*>(&Vs[kk][tx * 4]);
            float av[4] = {a.x, a.y, a.z, a.w};
            float bv[4] = {bb.x, bb.y, bb.z, bb.w};
#pragma unroll
            for (int i = 0; i < 4; i++)
#pragma unroll
                for (int j = 0; j < 4; j++)
                    acc[i][j] += av[i] * bv[j];
        }
        __syncthreads();
    }
#pragma unroll
    for (int i = 0; i < 4; i++) {
        int ii = i0 + ty * 4 + i;
        float4 o = make_float4(acc[i][0], acc[i][1], acc[i][2], acc[i][3]);
        *reinterpret_cast<float4*>(
            &oh[(size_t)(b * LL + ii) * HD + h * DK + tx * 4]) = o;
    }
}

// ---------------------------------------------------------------------------
extern "C" void kernel_launch(void* const* d_in, const int* in_sizes, int n_in,
                              void* d_out, int out_size)
{
    const float* Q  = (const float*)d_in[0];
    const float* K  = (const float*)d_in[1];
    const float* V  = (const float*)d_in[2];
    const int*   mask = (const int*)d_in[3];
    const float* Wq = (const float*)d_in[4];
    const float* bq = (const float*)d_in[5];
    const float* Wk = (const float*)d_in[6];
    const float* bk = (const float*)d_in[7];
    const float* Wv = (const float*)d_in[8];
    const float* bv = (const float*)d_in[9];
    const float* Wo = (const float*)d_in[10];
    const float* bo = (const float*)d_in[11];

    float* out  = (float*)d_out;          // [B, Lq, 512]
    float* attn = out + OUT0;             // [B, H, Lq, Lk]

    float *q, *k, *v, *oh, *rs;
    cudaGetSymbolAddress((void**)&q,  g_q);
    cudaGetSymbolAddress((void**)&k,  g_k);
    cudaGetSymbolAddress((void**)&v,  g_v);
    cudaGetSymbolAddress((void**)&oh, g_oh);
    cudaGetSymbolAddress((void**)&rs, g_rowsum);

    const int M = BB * LL;                // 8192
    cudaFuncSetAttribute(scores_mma_kernel,
                         cudaFuncAttributeMaxDynamicSharedMemorySize, SCORES_DYN);

    // 0) zero the rowsum accumulator
    zero_rowsum_kernel<<<NROWS / 256, 256>>>(rs);

    // 1) fused projections: [8192,512] @ [512,128] x3
    dim3 gp(HD / 64, M / 128, 3);
    qkv_kernel<<<gp, 256>>>(Q, K, V, Wq, Wk, Wv, bq, bk, bv, q, k, v);

    // 2) tensor-core scores + tanh clip + mask -> attn (raw) + rowsum atomics
    dim3 gs(LL / 128, LL / 128, BB * NH);
    scores_mma_kernel<<<gs, 256, SCORES_DYN>>>(q, k, mask, attn, rs);

    // 3) rowsum -> lse
    lse_kernel<<<NROWS / 256, 256>>>(rs);

    // 4) attn = s - lse (written back) ; oh = attn @ v
    dim3 ga(LL / 64, BB * NH);
    av_kernel<<<ga, 256>>>(attn, v, rs, oh);

    // 5) out = oh @ Wo + bo : [8192,128] @ [128,512]
    dim3 go(DM / 64, M / 128);
    gemm_bias_kernel<<<go, 256>>>(oh, Wo, bo, out, M, DM, HD);
}